// round 3
// baseline (speedup 1.0000x reference)
#include <cuda_runtime.h>
#include <math.h>

#define Nn   50000
#define Ee   1600000
#define Dh   64
#define Din  128
#define Gg   64
#define NCLS 10

// ---------------- scratch (static device globals; referenced ONLY in device code) -------
__device__ float g_xl[Nn * Dh];
__device__ float g_xr[Nn * Dh];
__device__ float g_h [Nn * Dh];
__device__ int   g_deg[Nn];
__device__ int   g_indptr[Nn + 1];
__device__ int   g_wpos[Nn];
__device__ int   g_csr_src[Ee];
__device__ float g_csr_attr[Ee];
__device__ float g_attrsum;
__device__ float g_pooled[Gg * Dh];
__device__ int   g_cnt[Gg];

// ---------------- zero per-call scratch ----------------
__global__ void zero_kernel() {
    int i = blockIdx.x * blockDim.x + threadIdx.x;
    if (i < Nn) g_deg[i] = 0;
    if (i < Gg * Dh) g_pooled[i] = 0.f;
    if (i < Gg) g_cnt[i] = 0;
    if (i == 0) g_attrsum = 0.f;
}

// ---------------- degree count + edge_attr sum ----------------
__global__ void count_kernel(const int* __restrict__ dst, const float* __restrict__ attr) {
    int e = blockIdx.x * blockDim.x + threadIdx.x;
    float v = 0.f;
    if (e < Ee) {
        atomicAdd(&g_deg[dst[e]], 1);
        v = attr[e];
    }
    #pragma unroll
    for (int o = 16; o; o >>= 1) v += __shfl_xor_sync(0xffffffffu, v, o);
    __shared__ float red[8];
    int lane = threadIdx.x & 31, wid = threadIdx.x >> 5;
    if (lane == 0) red[wid] = v;
    __syncthreads();
    if (threadIdx.x < 8) {
        float w = red[threadIdx.x];
        #pragma unroll
        for (int o = 4; o; o >>= 1) w += __shfl_xor_sync(0xffu, w, o);
        if (threadIdx.x == 0) atomicAdd(&g_attrsum, w);
    }
}

// ---------------- single-block exclusive scan over degrees ----------------
__global__ void scan_kernel() {
    __shared__ int warpsums[32];
    __shared__ int carry_s;
    int tid = threadIdx.x, lane = tid & 31, wid = tid >> 5;
    if (tid == 0) carry_s = 0;
    __syncthreads();
    for (int base = 0; base < Nn; base += 1024) {
        int i = base + tid;
        int v = (i < Nn) ? g_deg[i] : 0;
        int x = v;
        #pragma unroll
        for (int o = 1; o < 32; o <<= 1) {
            int y = __shfl_up_sync(0xffffffffu, x, o);
            if (lane >= o) x += y;
        }
        if (lane == 31) warpsums[wid] = x;
        __syncthreads();
        if (wid == 0) {
            int w = warpsums[lane];
            #pragma unroll
            for (int o = 1; o < 32; o <<= 1) {
                int y = __shfl_up_sync(0xffffffffu, w, o);
                if (lane >= o) w += y;
            }
            warpsums[lane] = w;
        }
        __syncthreads();
        int warpprefix = (wid > 0) ? warpsums[wid - 1] : 0;
        int excl = carry_s + warpprefix + x - v;
        if (i < Nn) { g_indptr[i] = excl; g_wpos[i] = excl; }
        __syncthreads();
        if (tid == 0) carry_s += warpsums[31];
        __syncthreads();
    }
    if (threadIdx.x == 0) g_indptr[Nn] = carry_s;
}

// ---------------- scatter edges into CSR-by-dst ----------------
__global__ void scatter_kernel(const int* __restrict__ src, const int* __restrict__ dst,
                               const float* __restrict__ attr) {
    int e = blockIdx.x * blockDim.x + threadIdx.x;
    if (e >= Ee) return;
    int d = dst[e];
    int p = atomicAdd(&g_wpos[d], 1);
    g_csr_src[p]  = src[e];
    g_csr_attr[p] = attr[e];
}

// ---------------- fused dual GEMM: g_xl = IN@Wl + bl, g_xr = IN@Wr + br ----------------
// USE_GH: read input rows from g_h (layer 2) instead of the X pointer (layer 1).
template <int K, bool USE_GH>
__global__ void gemm_dual(const float* __restrict__ X,
                          const float* __restrict__ Wl, const float* __restrict__ bl,
                          const float* __restrict__ Wr, const float* __restrict__ br) {
    extern __shared__ float sm[];
    float* sWl = sm;
    float* sWr = sm + K * Dh;
    float* sX  = sm + 2 * K * Dh;   // [64][K]
    int tid = threadIdx.x;
    for (int idx = tid; idx < K * Dh; idx += 256) { sWl[idx] = Wl[idx]; sWr[idx] = Wr[idx]; }
    int row0 = blockIdx.x * 64;
    const float* __restrict__ IN = USE_GH ? g_h : X;
    for (int idx = tid; idx < 64 * K; idx += 256) {
        int r = idx / K, k = idx - r * K;
        int gr = row0 + r;
        sX[idx] = (gr < Nn) ? IN[gr * K + k] : 0.f;
    }
    __syncthreads();
    int warp = tid >> 5, lane = tid & 31;
    int rbase = warp * 8;
    float al0[8], al1[8], ar0[8], ar1[8];
    #pragma unroll
    for (int j = 0; j < 8; j++) { al0[j] = al1[j] = ar0[j] = ar1[j] = 0.f; }
    #pragma unroll 4
    for (int k = 0; k < K; k++) {
        float wl0 = sWl[k * Dh + lane],      wl1 = sWl[k * Dh + 32 + lane];
        float wr0 = sWr[k * Dh + lane],      wr1 = sWr[k * Dh + 32 + lane];
        #pragma unroll
        for (int j = 0; j < 8; j++) {
            float xv = sX[(rbase + j) * K + k];
            al0[j] += xv * wl0; al1[j] += xv * wl1;
            ar0[j] += xv * wr0; ar1[j] += xv * wr1;
        }
    }
    float b0 = bl[lane], b1 = bl[32 + lane], c0 = br[lane], c1 = br[32 + lane];
    #pragma unroll
    for (int j = 0; j < 8; j++) {
        int gr = row0 + rbase + j;
        if (gr < Nn) {
            g_xl[gr * Dh + lane]      = al0[j] + b0;
            g_xl[gr * Dh + 32 + lane] = al1[j] + b1;
            g_xr[gr * Dh + lane]      = ar0[j] + c0;
            g_xr[gr * Dh + 32 + lane] = ar1[j] + c1;
        }
    }
}

// ---------------- GATv2: warp per destination node, online softmax; writes g_h ---------
__global__ void gat_kernel(const float* __restrict__ We, const float* __restrict__ att,
                           const float* __restrict__ bias) {
    int warp = (blockIdx.x * blockDim.x + threadIdx.x) >> 5;
    int lane = threadIdx.x & 31;
    if (warp >= Nn) return;
    int i = warp;
    float xr0 = g_xr[i * Dh + lane], xr1 = g_xr[i * Dh + 32 + lane];
    float we0 = We[lane], we1 = We[32 + lane];
    float at0 = att[lane], at1 = att[32 + lane];
    float mean_attr = g_attrsum * (1.0f / Ee);
    float m = -INFINITY, s = 0.f, a0 = 0.f, a1 = 0.f;
    int beg = g_indptr[i], end = g_indptr[i + 1];
    for (int e = beg; e <= end; ++e) {        // e == end -> self loop
        int src; float attr;
        if (e < end) { src = g_csr_src[e]; attr = g_csr_attr[e]; }
        else         { src = i;            attr = mean_attr;     }
        float xl0 = g_xl[src * Dh + lane], xl1 = g_xl[src * Dh + 32 + lane];
        float t0 = xl0 + xr0 + attr * we0;
        float t1 = xl1 + xr1 + attr * we1;
        t0 = t0 > 0.f ? t0 : 0.2f * t0;
        t1 = t1 > 0.f ? t1 : 0.2f * t1;
        float p = t0 * at0 + t1 * at1;
        #pragma unroll
        for (int o = 16; o; o >>= 1) p += __shfl_xor_sync(0xffffffffu, p, o);
        if (p > m) {                          // warp-uniform branch
            float sc = __expf(m - p);         // exp(-inf)=0 on first edge
            s  = s  * sc + 1.f;
            a0 = a0 * sc + xl0;
            a1 = a1 * sc + xl1;
            m = p;
        } else {
            float z = __expf(p - m);
            s += z;
            a0 += z * xl0;
            a1 += z * xl1;
        }
    }
    float inv = 1.f / (s + 1e-16f);
    float o0 = a0 * inv + bias[lane];
    float o1 = a1 * inv + bias[32 + lane];
    o0 = o0 > 0.f ? o0 : expm1f(o0);          // ELU
    o1 = o1 > 0.f ? o1 : expm1f(o1);
    g_h[i * Dh + lane]      = o0;
    g_h[i * Dh + 32 + lane] = o1;
}

// ---------------- mean pool per graph (batch is sorted) ----------------
__global__ void pool_kernel(const int* __restrict__ batch) {
    int d = threadIdx.x;                 // 64 threads
    int n0 = blockIdx.x * 256;
    int n1 = n0 + 256; if (n1 > Nn) n1 = Nn;
    float acc = 0.f; int curg = -1; int c = 0;
    for (int n = n0; n < n1; ++n) {
        int g = batch[n];
        if (g != curg) {
            if (curg >= 0) {
                atomicAdd(&g_pooled[curg * Dh + d], acc);
                if (d == 0) atomicAdd(&g_cnt[curg], c);
            }
            curg = g; acc = 0.f; c = 0;
        }
        acc += g_h[n * Dh + d];
        ++c;
    }
    if (curg >= 0) {
        atomicAdd(&g_pooled[curg * Dh + d], acc);
        if (d == 0) atomicAdd(&g_cnt[curg], c);
    }
}

// ---------------- classifier: out[g][c] = mean_pooled @ Wc + bc ----------------
__global__ void cls_kernel(const float* __restrict__ Wc, const float* __restrict__ bc,
                           float* __restrict__ out) {
    int t = threadIdx.x;                 // 640 threads
    int g = t / NCLS, c = t - g * NCLS;
    float invc = 1.f / fmaxf((float)g_cnt[g], 1.f);
    float acc = bc[c];
    #pragma unroll 8
    for (int d = 0; d < Dh; ++d)
        acc += g_pooled[g * Dh + d] * invc * Wc[d * NCLS + c];
    out[t] = acc;
}

// ---------------- launch ----------------
extern "C" void kernel_launch(void* const* d_in, const int* in_sizes, int n_in,
                              void* d_out, int out_size) {
    const float* x    = (const float*)d_in[0];
    const int*   ei   = (const int*)  d_in[1];
    const float* eatt = (const float*)d_in[2];
    const int*   batch= (const int*)  d_in[3];
    const float* Wl1 = (const float*)d_in[4],  *bl1 = (const float*)d_in[5];
    const float* Wr1 = (const float*)d_in[6],  *br1 = (const float*)d_in[7];
    const float* We1 = (const float*)d_in[8],  *att1= (const float*)d_in[9];
    const float* b1  = (const float*)d_in[10];
    const float* Wl2 = (const float*)d_in[11], *bl2 = (const float*)d_in[12];
    const float* Wr2 = (const float*)d_in[13], *br2 = (const float*)d_in[14];
    const float* We2 = (const float*)d_in[15], *att2= (const float*)d_in[16];
    const float* b2  = (const float*)d_in[17];
    const float* Wc  = (const float*)d_in[18], *bc  = (const float*)d_in[19];
    float* out = (float*)d_out;

    const int* src = ei;
    const int* dst = ei + Ee;

    // raise dynamic smem limits (idempotent, not a stream op — safe during capture)
    int smem1 = (2 * Din * Dh + 64 * Din) * (int)sizeof(float);   // 96 KB
    int smem2 = (2 * Dh * Dh + 64 * Dh) * (int)sizeof(float);     // 48 KB
    cudaFuncSetAttribute(gemm_dual<Din, false>,
                         cudaFuncAttributeMaxDynamicSharedMemorySize, smem1);
    cudaFuncSetAttribute(gemm_dual<Dh, true>,
                         cudaFuncAttributeMaxDynamicSharedMemorySize, smem2);

    // 1. zero per-call scratch
    zero_kernel<<<(Nn + 255) / 256, 256>>>();
    // 2. CSR build
    count_kernel<<<(Ee + 255) / 256, 256>>>(dst, eatt);
    scan_kernel<<<1, 1024>>>();
    scatter_kernel<<<(Ee + 255) / 256, 256>>>(src, dst, eatt);
    // 3. layer 1
    gemm_dual<Din, false><<<(Nn + 63) / 64, 256, smem1>>>(x, Wl1, bl1, Wr1, br1);
    gat_kernel<<<(Nn + 7) / 8, 256>>>(We1, att1, b1);
    // 4. layer 2
    gemm_dual<Dh, true><<<(Nn + 63) / 64, 256, smem2>>>(nullptr, Wl2, bl2, Wr2, br2);
    gat_kernel<<<(Nn + 7) / 8, 256>>>(We2, att2, b2);
    // 5. pool + classify
    pool_kernel<<<(Nn + 255) / 256, 64>>>(batch);
    cls_kernel<<<1, Gg * NCLS>>>(Wc, bc, out);
}